// round 13
// baseline (speedup 1.0000x reference)
#include <cuda_runtime.h>

#define NPT 16384
#define BB  2

__device__ float g_f [BB*NPT*64];
__device__ float g_q [BB*NPT*64];     // QS = s0*q - t0
__device__ float g_kv[BB*NPT*128];    // [row][0:64]=s0*(k+pr), [64:128]=v+pr
__device__ float g_xm[BB*NPT*64];

__device__ float g_W1f[32*64];
__device__ float g_t1[64];
__device__ float g_WqT[64*64], g_WkT[64*64], g_WvT[64*64];
__device__ float g_bqv[64], g_bkv[64], g_bvv[64];
__device__ float g_Wp1f[9], g_tp[3];
__device__ float g_Wp2b[64*4];
__device__ float g_s0t0[64*2];
__device__ unsigned g_Ww1p[64*4];     // bf16-packed Ww1: word i of ch = (w[2i] | w[2i+1]<<16)
__device__ float g_tw1[8], g_Ww2m[64], g_bw2v[8];
__device__ float g_smt[64*2];
__device__ float g_W2T[64*64], g_t2[64];

__device__ __forceinline__ float lrelu(float x) { return fmaxf(x, 0.2f*x); }
__device__ __forceinline__ unsigned bf16r(float x) {   // round-to-nearest-even bf16
    unsigned u = __float_as_uint(x);
    u += 0x7fffu + ((u >> 16) & 1u);
    return u >> 16;
}

// ---------------- prep: 64 blocks x 64 threads ------------------------------
__global__ void k_prep(const float* __restrict__ W1,  const float* __restrict__ bn1,
                       const float* __restrict__ Wq,  const float* __restrict__ bq,
                       const float* __restrict__ Wk,  const float* __restrict__ bk,
                       const float* __restrict__ Wv,  const float* __restrict__ bv,
                       const float* __restrict__ Wp1, const float* __restrict__ bnp1,
                       const float* __restrict__ Wp2, const float* __restrict__ bp2,
                       const float* __restrict__ bnw0,const float* __restrict__ Ww1,
                       const float* __restrict__ bnw1,const float* __restrict__ Ww2,
                       const float* __restrict__ bw2, const float* __restrict__ bn_mid,
                       const float* __restrict__ W2,  const float* __restrict__ bn2)
{
    int c = blockIdx.x;   // 0..63 output channel
    int i = threadIdx.x;  // 0..63 input channel
    float s1 = bn1[c] * rsqrtf(bn1[192+c] + 1e-5f);
    float s2 = bn2[c] * rsqrtf(bn2[192+c] + 1e-5f);
    if (i < 32) g_W1f[i*64+c] = W1[c*32+i]*s1;
    g_WqT[i*64+c] = Wq[c*64+i];
    g_WkT[i*64+c] = Wk[c*64+i];
    g_WvT[i*64+c] = Wv[c*64+i];
    g_W2T[i*64+c] = W2[c*64+i]*s2;
    if (i < 4) {
        int j0 = 2*i, j1 = 2*i+1;
        float sw0 = bnw1[j0] * rsqrtf(bnw1[24+j0] + 1e-5f);
        float sw1 = bnw1[j1] * rsqrtf(bnw1[24+j1] + 1e-5f);
        float w0 = Ww1[j0*64+c]*sw0;
        float w1 = Ww1[j1*64+c]*sw1;
        g_Ww1p[c*4+i] = bf16r(w0) | (bf16r(w1) << 16);
    }
    if (i == 0) {
        g_t1[c] = bn1[64+c] - bn1[128+c]*s1;
        g_bqv[c] = bq[c]; g_bkv[c] = bk[c]; g_bvv[c] = bv[c];
        g_Wp2b[c*4+0] = Wp2[c*3+0];
        g_Wp2b[c*4+1] = Wp2[c*3+1];
        g_Wp2b[c*4+2] = Wp2[c*3+2];
        g_Wp2b[c*4+3] = bp2[c];
        float s0 = bnw0[c] * rsqrtf(bnw0[192+c] + 1e-5f);
        g_s0t0[c*2+0] = s0;
        g_s0t0[c*2+1] = bnw0[64+c] - bnw0[128+c]*s0;
        float sm = bn_mid[c] * rsqrtf(bn_mid[192+c] + 1e-5f);
        g_smt[c*2+0] = sm;
        g_smt[c*2+1] = bn_mid[64+c] - bn_mid[128+c]*sm;
        g_t2[c] = bn2[64+c] - bn2[128+c]*s2;
    }
    if (c == 0) {
        if (i < 3) {
            float sp = bnp1[i] * rsqrtf(bnp1[9+i] + 1e-5f);
            g_Wp1f[i*3+0] = Wp1[i*3+0]*sp;
            g_Wp1f[i*3+1] = Wp1[i*3+1]*sp;
            g_Wp1f[i*3+2] = Wp1[i*3+2]*sp;
            g_tp[i] = bnp1[3+i] - bnp1[6+i]*sp;
        }
        if (i < 8) {
            float sw = bnw1[i] * rsqrtf(bnw1[24+i] + 1e-5f);
            g_tw1[i]  = bnw1[8+i] - bnw1[16+i]*sw;
            g_bw2v[i] = bw2[i];
        }
        g_Ww2m[i] = Ww2[i];
    }
}

// ---------------- fused projections: f, QS, K', V' (scalar float4 GEMMs) ----
__global__ void __launch_bounds__(256) k_proj(const float* __restrict__ feat,
                                              const float* __restrict__ xyz)
{
    __shared__ float sfe[32*68];
    __shared__ float sf [64*68];   // f tile, [c][p]
    __shared__ float sh [64*4];    // pos-MLP hidden per point
    int t  = threadIdx.x;
    int b  = blockIdx.y;
    int n0 = blockIdx.x * 64;
    size_t base = (size_t)b*NPT + n0;

    #pragma unroll
    for (int r = 0; r < 8; r++) {
        int li = r*256 + t;
        int i = li >> 6, p = li & 63;
        sfe[i*68+p] = feat[(size_t)(b*32 + i)*NPT + n0 + p];
    }
    if (t < 64) {
        const float* xr = xyz + (base + t)*3;
        float X = xr[0], Y = xr[1], Z = xr[2];
        sh[t*4+0] = fmaxf(fmaf(g_Wp1f[0], X, fmaf(g_Wp1f[1], Y, fmaf(g_Wp1f[2], Z, g_tp[0]))), 0.f);
        sh[t*4+1] = fmaxf(fmaf(g_Wp1f[3], X, fmaf(g_Wp1f[4], Y, fmaf(g_Wp1f[5], Z, g_tp[1]))), 0.f);
        sh[t*4+2] = fmaxf(fmaf(g_Wp1f[6], X, fmaf(g_Wp1f[7], Y, fmaf(g_Wp1f[8], Z, g_tp[2]))), 0.f);
    }
    __syncthreads();

    int cc = t & 15, pg = t >> 4;
    int cb = 4*cc, pb = 4*pg;

    // ---- GEMM1: f = relu(W1f x + t1); write g_f and sf
    {
        float af[4][4];
        #pragma unroll
        for (int x = 0; x < 4; x++)
            #pragma unroll
            for (int y = 0; y < 4; y++) af[x][y] = 0.f;

        #pragma unroll
        for (int i = 0; i < 32; i++) {
            float4 w  = *(const float4*)&g_W1f[i*64 + cb];
            float4 fv = *(const float4*)&sfe[i*68 + pb];
            float wc[4] = {w.x,w.y,w.z,w.w};
            float fp[4] = {fv.x,fv.y,fv.z,fv.w};
            #pragma unroll
            for (int ch = 0; ch < 4; ch++)
                #pragma unroll
                for (int pp = 0; pp < 4; pp++)
                    af[ch][pp] = fmaf(wc[ch], fp[pp], af[ch][pp]);
        }
        float4 t1v = *(const float4*)&g_t1[cb];
        float tb[4] = {t1v.x, t1v.y, t1v.z, t1v.w};
        #pragma unroll
        for (int ch = 0; ch < 4; ch++)
            #pragma unroll
            for (int pp = 0; pp < 4; pp++) {
                float v = fmaxf(af[ch][pp] + tb[ch], 0.f);
                af[ch][pp] = v;
                sf[(cb+ch)*68 + pb + pp] = v;
            }
        #pragma unroll
        for (int pp = 0; pp < 4; pp++)
            *(float4*)&g_f[(base + pb + pp)*64 + cb] =
                make_float4(af[0][pp], af[1][pp], af[2][pp], af[3][pp]);
    }
    __syncthreads();

    // ---- projections: z=0 QS, z=1 K', z=2 V'
    #pragma unroll
    for (int z = 0; z < 3; z++) {
        const float* W    = (z == 0) ? g_WqT : (z == 1) ? g_WkT : g_WvT;
        const float* bias = (z == 0) ? g_bqv : (z == 1) ? g_bkv : g_bvv;

        float a[4][4];
        #pragma unroll
        for (int x = 0; x < 4; x++)
            #pragma unroll
            for (int y = 0; y < 4; y++) a[x][y] = 0.f;

        #pragma unroll 8
        for (int c = 0; c < 64; c++) {
            float4 w  = *(const float4*)&W[c*64 + cb];
            float4 fv = *(const float4*)&sf[c*68 + pb];
            float wc[4] = {w.x,w.y,w.z,w.w};
            float fp[4] = {fv.x,fv.y,fv.z,fv.w};
            #pragma unroll
            for (int ch = 0; ch < 4; ch++)
                #pragma unroll
                for (int pp = 0; pp < 4; pp++)
                    a[ch][pp] = fmaf(wc[ch], fp[pp], a[ch][pp]);
        }
        float4 bb = *(const float4*)&bias[cb];
        float bvr[4] = {bb.x, bb.y, bb.z, bb.w};

        if (z == 0) {
            #pragma unroll
            for (int pp = 0; pp < 4; pp++) {
                float o[4];
                #pragma unroll
                for (int ch = 0; ch < 4; ch++) {
                    float2 st = *(const float2*)&g_s0t0[(cb+ch)*2];
                    o[ch] = fmaf(st.x, a[ch][pp] + bvr[ch], -st.y);
                }
                *(float4*)&g_q[(base + pb + pp)*64 + cb] =
                    make_float4(o[0], o[1], o[2], o[3]);
            }
        } else {
            float* dst = (z == 1) ? g_kv : (g_kv + 64);
            #pragma unroll
            for (int pp = 0; pp < 4; pp++) {
                float h0 = sh[(pb+pp)*4+0], h1 = sh[(pb+pp)*4+1], h2 = sh[(pb+pp)*4+2];
                float o[4];
                #pragma unroll
                for (int ch = 0; ch < 4; ch++) {
                    float4 wp = *(const float4*)&g_Wp2b[(cb+ch)*4];
                    float pr = fmaf(wp.x, h0, fmaf(wp.y, h1, fmaf(wp.z, h2, wp.w)));
                    float val = a[ch][pp] + bvr[ch] + pr;
                    if (z == 1) val *= g_s0t0[(cb+ch)*2];
                    o[ch] = val;
                }
                *(float4*)&dst[(base + pb + pp)*128 + cb] =
                    make_float4(o[0], o[1], o[2], o[3]);
            }
        }
    }
}

// ---------------- attention core: writes xm (point-major) -------------------
#define WPB 4
__global__ void __launch_bounds__(128) k_attn(const int* __restrict__ nidx)
{
    __shared__ float skv[WPB][16*64];   // K' only: 16 rows x 256B, swizzled
    __shared__ float swt[WPB][132];
    __shared__ unsigned sWw1p[256];     // bf16-packed Ww1: 4 words per channel
    __shared__ float sWw2[64];
    __shared__ float sAux[16];

    int t = threadIdx.x;
    sWw1p[t]       = g_Ww1p[t];
    sWw1p[128+t]   = g_Ww1p[128+t];
    if (t < 64)    sWw2[t] = g_Ww2m[t];
    if (t < 8)   { sAux[t] = g_tw1[t]; sAux[8+t] = g_bw2v[t]; }
    __syncthreads();

    int warp = t >> 5, l = t & 31;
    int pid = blockIdx.x * WPB + warp;
    int b   = pid >> 14;
    int n   = pid & 16383;
    size_t rowb  = (size_t)b * NPT;
    size_t pbase = (rowb + n) * 64;

    int k = l & 15, h = l >> 4;
    int c0 = 32 * h;

    const int* nrow = nidx + (size_t)pid*16;
    int myidx = (l < 16) ? __ldg(nrow + l) : 0;

    // cooperative gather of K' via cp.async (no register round-trip)
    float* skvw = skv[warp];
    int i2 = l >> 4, ch16 = l & 15;
    #pragma unroll
    for (int i = 0; i < 8; i++) {
        int row = 2*i + i2;
        int r = __shfl_sync(0xffffffffu, myidx, row);
        const float4* src = (const float4*)(g_kv + (rowb + r)*128) + ch16;
        int pp = ch16 ^ (row & 7);
        unsigned dst = (unsigned)__cvta_generic_to_shared(&skvw[row*64 + pp*4]);
        asm volatile("cp.async.cg.shared.global [%0], [%1], 16;" :: "r"(dst), "l"(src));
    }
    asm volatile("cp.async.commit_group;" ::: "memory");
    asm volatile("cp.async.wait_group 0;" ::: "memory");
    __syncwarp();

    // phase 1: u = lrelu(K' - QS), accumulate Ww1 partials over own 32 channels
    float w1p[8];
    #pragma unroll
    for (int j = 0; j < 8; j++) w1p[j] = 0.f;

    int sw8 = k & 7;
    #pragma unroll
    for (int s = 0; s < 8; s++) {
        int c = c0 + 4*s;
        float4 kk = *(const float4*)&skvw[k*64 + ((h*8 + s) ^ sw8)*4];
        float4 qs = __ldg((const float4*)(g_q + pbase + c));
        float kr[4] = {kk.x,kk.y,kk.z,kk.w};
        float qr[4] = {qs.x,qs.y,qs.z,qs.w};
        #pragma unroll
        for (int e = 0; e < 4; e++) {
            int ch = c + e;
            float u = lrelu(kr[e] - qr[e]);
            uint4 wp = *(const uint4*)&sWw1p[ch*4];
            float a0 = __uint_as_float(wp.x << 16);
            float a1 = __uint_as_float(wp.x & 0xffff0000u);
            float a2 = __uint_as_float(wp.y << 16);
            float a3 = __uint_as_float(wp.y & 0xffff0000u);
            float a4 = __uint_as_float(wp.z << 16);
            float a5 = __uint_as_float(wp.z & 0xffff0000u);
            float a6 = __uint_as_float(wp.w << 16);
            float a7 = __uint_as_float(wp.w & 0xffff0000u);
            w1p[0] = fmaf(a0, u, w1p[0]); w1p[1] = fmaf(a1, u, w1p[1]);
            w1p[2] = fmaf(a2, u, w1p[2]); w1p[3] = fmaf(a3, u, w1p[3]);
            w1p[4] = fmaf(a4, u, w1p[4]); w1p[5] = fmaf(a5, u, w1p[5]);
            w1p[6] = fmaf(a6, u, w1p[6]); w1p[7] = fmaf(a7, u, w1p[7]);
        }
    }

    #pragma unroll
    for (int j = 0; j < 8; j++)
        w1p[j] += __shfl_xor_sync(0xffffffffu, w1p[j], 16);

    // tw1/bw2 as vector loads; Ww2 rows hoisted into registers
    float4 tA = *(const float4*)&sAux[0];
    float4 tB = *(const float4*)&sAux[4];
    float tw[8] = {tA.x,tA.y,tA.z,tA.w,tB.x,tB.y,tB.z,tB.w};
    float w1v[8];
    #pragma unroll
    for (int j = 0; j < 8; j++) w1v[j] = fmaxf(w1p[j] + tw[j], 0.f);

    float2 bw = *(const float2*)&sAux[8 + 4*h + 0];
    float2 bw2_ = *(const float2*)&sAux[8 + 4*h + 2];
    float bwr[4] = {bw.x, bw.y, bw2_.x, bw2_.y};

    float wt[4];
    #pragma unroll
    for (int jj = 0; jj < 4; jj++) {
        int j = 4*h + jj;
        float4 rA = *(const float4*)&sWw2[j*8];
        float4 rB = *(const float4*)&sWw2[j*8 + 4];
        float a = bwr[jj];
        a = fmaf(rA.x, w1v[0], a); a = fmaf(rA.y, w1v[1], a);
        a = fmaf(rA.z, w1v[2], a); a = fmaf(rA.w, w1v[3], a);
        a = fmaf(rB.x, w1v[4], a); a = fmaf(rB.y, w1v[5], a);
        a = fmaf(rB.z, w1v[6], a); a = fmaf(rB.w, w1v[7], a);
        wt[jj] = a;
    }
    *(float4*)&swt[warp][k*8 + 4*h] = make_float4(wt[0], wt[1], wt[2], wt[3]);
    __syncwarp();

    // softmax over K
    {
        int j = l >> 2, kq = l & 3;
        float v0 = swt[warp][(4*kq+0)*8 + j];
        float v1 = swt[warp][(4*kq+1)*8 + j];
        float v2 = swt[warp][(4*kq+2)*8 + j];
        float v3 = swt[warp][(4*kq+3)*8 + j];
        float mx = fmaxf(fmaxf(v0, v1), fmaxf(v2, v3));
        mx = fmaxf(mx, __shfl_xor_sync(0xffffffffu, mx, 1));
        mx = fmaxf(mx, __shfl_xor_sync(0xffffffffu, mx, 2));
        float e0 = __expf(v0 - mx), e1 = __expf(v1 - mx);
        float e2 = __expf(v2 - mx), e3 = __expf(v3 - mx);
        float sm = e0 + e1 + e2 + e3;
        sm += __shfl_xor_sync(0xffffffffu, sm, 1);
        sm += __shfl_xor_sync(0xffffffffu, sm, 2);
        float inv = __fdividef(1.f, sm);
        swt[warp][(4*kq+0)*8 + j] = e0 * inv;
        swt[warp][(4*kq+1)*8 + j] = e1 * inv;
        swt[warp][(4*kq+2)*8 + j] = e2 * inv;
        swt[warp][(4*kq+3)*8 + j] = e3 * inv;
    }
    __syncwarp();

    // phase 3: lane owns channels 2l, 2l+1; V' read from global (L2-hot)
    int cc0 = 2*l;
    int j0 = cc0 & 7;
    float acc0 = 0.f, acc1 = 0.f;
    #pragma unroll
    for (int kk2 = 0; kk2 < 16; kk2++) {
        float2 wv = *(const float2*)&swt[warp][kk2*8 + j0];
        int r = __shfl_sync(0xffffffffu, myidx, kk2);
        float2 vv = __ldg((const float2*)(g_kv + (rowb + r)*128 + 64 + cc0));
        acc0 = fmaf(wv.x, vv.x, acc0);
        acc1 = fmaf(wv.y, vv.y, acc1);
    }

    float4 sm4 = *(const float4*)(g_smt + 4*l);
    float xa = lrelu(fmaf(sm4.x, acc0, sm4.y));
    float xb = lrelu(fmaf(sm4.z, acc1, sm4.w));
    *(float2*)&g_xm[pbase + cc0] = make_float2(xa, xb);
}

// ---------------- conv2 + residual + lrelu, tiled GEMM (256 threads) --------
__global__ void __launch_bounds__(256) k_out(float* __restrict__ out)
{
    __shared__ float sbuf[64*68];
    int t  = threadIdx.x;
    int b  = blockIdx.y;
    int n0 = blockIdx.x * 64;
    size_t base = (size_t)b*NPT + n0;

    int p = t & 63, chunk = t >> 6;
    #pragma unroll
    for (int j = 0; j < 4; j++) {
        int ch = chunk*16 + 4*j;
        float4 v = *(const float4*)&g_xm[(base + p)*64 + ch];
        sbuf[(ch+0)*68+p] = v.x;
        sbuf[(ch+1)*68+p] = v.y;
        sbuf[(ch+2)*68+p] = v.z;
        sbuf[(ch+3)*68+p] = v.w;
    }
    __syncthreads();

    int cc = t & 15, pg = t >> 4;
    int cb = 4*cc, pb = 4*pg;

    float a[4][4];
    #pragma unroll
    for (int x = 0; x < 4; x++)
        #pragma unroll
        for (int y = 0; y < 4; y++) a[x][y] = 0.f;

    #pragma unroll 8
    for (int c = 0; c < 64; c++) {
        float4 w  = *(const float4*)&g_W2T[c*64 + cb];
        float4 xv = *(const float4*)&sbuf[c*68 + pb];
        float wc[4] = {w.x,w.y,w.z,w.w};
        float xp[4] = {xv.x,xv.y,xv.z,xv.w};
        #pragma unroll
        for (int ch = 0; ch < 4; ch++)
            #pragma unroll
            for (int pp = 0; pp < 4; pp++)
                a[ch][pp] = fmaf(wc[ch], xp[pp], a[ch][pp]);
    }
    __syncthreads();   // done reading sbuf, reuse as output stage

    float4 t2v = *(const float4*)&g_t2[cb];
    float tb[4] = {t2v.x, t2v.y, t2v.z, t2v.w};
    #pragma unroll
    for (int pp = 0; pp < 4; pp++) {
        float4 fv = *(const float4*)&g_f[(base + pb + pp)*64 + cb];
        float fr[4] = {fv.x, fv.y, fv.z, fv.w};
        #pragma unroll
        for (int ch = 0; ch < 4; ch++)
            sbuf[(cb+ch)*68 + pb + pp] = lrelu(a[ch][pp] + tb[ch] + fr[ch]);
    }
    __syncthreads();

    int cO = t >> 2, q = t & 3;
    #pragma unroll
    for (int i = 0; i < 4; i++) {
        float4 vq = *(const float4*)&sbuf[cO*68 + q*16 + 4*i];
        *(float4*)&out[((size_t)(b*64 + cO))*NPT + n0 + q*16 + 4*i] = vq;
    }
}

extern "C" void kernel_launch(void* const* d_in, const int* in_sizes, int n_in,
                              void* d_out, int out_size)
{
    const float* feature = (const float*)d_in[0];
    const float* xyz     = (const float*)d_in[1];
    const float* W1      = (const float*)d_in[2];
    const float* bn1     = (const float*)d_in[3];
    const float* Wq      = (const float*)d_in[4];
    const float* bq      = (const float*)d_in[5];
    const float* Wk      = (const float*)d_in[6];
    const float* bk      = (const float*)d_in[7];
    const float* Wv      = (const float*)d_in[8];
    const float* bv      = (const float*)d_in[9];
    const float* Wp1     = (const float*)d_in[10];
    const float* bnp1    = (const float*)d_in[11];
    const float* Wp2     = (const float*)d_in[12];
    const float* bp2     = (const float*)d_in[13];
    const float* bnw0    = (const float*)d_in[14];
    const float* Ww1     = (const float*)d_in[15];
    const float* bnw1    = (const float*)d_in[16];
    const float* Ww2     = (const float*)d_in[17];
    const float* bw2     = (const float*)d_in[18];
    const float* bn_mid  = (const float*)d_in[19];
    const float* W2      = (const float*)d_in[20];
    const float* bn2     = (const float*)d_in[21];
    const int*   nidx    = (const int*)d_in[22];
    float* out = (float*)d_out;

    k_prep<<<64, 64>>>(W1, bn1, Wq, bq, Wk, bk, Wv, bv, Wp1, bnp1, Wp2, bp2,
                       bnw0, Ww1, bnw1, Ww2, bw2, bn_mid, W2, bn2);
    dim3 gf(NPT/64, BB);
    k_proj<<<gf, 256>>>(feature, xyz);
    k_attn<<<(BB*NPT)/WPB, 128>>>(nidx);
    k_out<<<gf, 256>>>(out);
}

// round 14
// speedup vs baseline: 1.0006x; 1.0006x over previous
#include <cuda_runtime.h>

#define NPT 16384
#define BB  2

__device__ float g_f [BB*NPT*64];
__device__ float g_q [BB*NPT*64];     // QS = s0*q - t0
__device__ float g_kv[BB*NPT*128];    // [row][0:64]=s0*(k+pr), [64:128]=v+pr
__device__ float g_xm[BB*NPT*64];

__device__ float g_W1f[32*64];
__device__ float g_t1[64];
__device__ float g_WqT[64*64], g_WkT[64*64], g_WvT[64*64];
__device__ float g_bqv[64], g_bkv[64], g_bvv[64];
__device__ float g_Wp1f[9], g_tp[3];
__device__ float g_Wp2b[64*4];
__device__ float g_s0t0[64*2];
__device__ float g_Ww1f[64*8];
__device__ float g_tw1[8], g_Ww2m[64], g_bw2v[8];
__device__ float g_smt[64*2];
__device__ float g_W2T[64*64], g_t2[64];

__device__ __forceinline__ float lrelu(float x) { return fmaxf(x, 0.2f*x); }

// ---------------- prep: 64 blocks x 64 threads ------------------------------
__global__ void k_prep(const float* __restrict__ W1,  const float* __restrict__ bn1,
                       const float* __restrict__ Wq,  const float* __restrict__ bq,
                       const float* __restrict__ Wk,  const float* __restrict__ bk,
                       const float* __restrict__ Wv,  const float* __restrict__ bv,
                       const float* __restrict__ Wp1, const float* __restrict__ bnp1,
                       const float* __restrict__ Wp2, const float* __restrict__ bp2,
                       const float* __restrict__ bnw0,const float* __restrict__ Ww1,
                       const float* __restrict__ bnw1,const float* __restrict__ Ww2,
                       const float* __restrict__ bw2, const float* __restrict__ bn_mid,
                       const float* __restrict__ W2,  const float* __restrict__ bn2)
{
    int c = blockIdx.x;   // 0..63 output channel
    int i = threadIdx.x;  // 0..63 input channel
    float s1 = bn1[c] * rsqrtf(bn1[192+c] + 1e-5f);
    float s2 = bn2[c] * rsqrtf(bn2[192+c] + 1e-5f);
    if (i < 32) g_W1f[i*64+c] = W1[c*32+i]*s1;
    g_WqT[i*64+c] = Wq[c*64+i];
    g_WkT[i*64+c] = Wk[c*64+i];
    g_WvT[i*64+c] = Wv[c*64+i];
    g_W2T[i*64+c] = W2[c*64+i]*s2;
    if (i < 8) {
        float sw = bnw1[i] * rsqrtf(bnw1[24+i] + 1e-5f);
        g_Ww1f[c*8+i] = Ww1[i*64+c]*sw;
    }
    if (i == 0) {
        g_t1[c] = bn1[64+c] - bn1[128+c]*s1;
        g_bqv[c] = bq[c]; g_bkv[c] = bk[c]; g_bvv[c] = bv[c];
        g_Wp2b[c*4+0] = Wp2[c*3+0];
        g_Wp2b[c*4+1] = Wp2[c*3+1];
        g_Wp2b[c*4+2] = Wp2[c*3+2];
        g_Wp2b[c*4+3] = bp2[c];
        float s0 = bnw0[c] * rsqrtf(bnw0[192+c] + 1e-5f);
        g_s0t0[c*2+0] = s0;
        g_s0t0[c*2+1] = bnw0[64+c] - bnw0[128+c]*s0;
        float sm = bn_mid[c] * rsqrtf(bn_mid[192+c] + 1e-5f);
        g_smt[c*2+0] = sm;
        g_smt[c*2+1] = bn_mid[64+c] - bn_mid[128+c]*sm;
        g_t2[c] = bn2[64+c] - bn2[128+c]*s2;
    }
    if (c == 0) {
        if (i < 3) {
            float sp = bnp1[i] * rsqrtf(bnp1[9+i] + 1e-5f);
            g_Wp1f[i*3+0] = Wp1[i*3+0]*sp;
            g_Wp1f[i*3+1] = Wp1[i*3+1]*sp;
            g_Wp1f[i*3+2] = Wp1[i*3+2]*sp;
            g_tp[i] = bnp1[3+i] - bnp1[6+i]*sp;
        }
        if (i < 8) {
            float sw = bnw1[i] * rsqrtf(bnw1[24+i] + 1e-5f);
            g_tw1[i]  = bnw1[8+i] - bnw1[16+i]*sw;
            g_bw2v[i] = bw2[i];
        }
        g_Ww2m[i] = Ww2[i];
    }
}

// ---------------- fused projections: f, QS, K', V' (scalar float4 GEMMs) ----
__global__ void __launch_bounds__(256) k_proj(const float* __restrict__ feat,
                                              const float* __restrict__ xyz)
{
    __shared__ float sfe[32*68];
    __shared__ float sf [64*68];   // f tile, [c][p]
    __shared__ float sh [64*4];    // pos-MLP hidden per point
    int t  = threadIdx.x;
    int b  = blockIdx.y;
    int n0 = blockIdx.x * 64;
    size_t base = (size_t)b*NPT + n0;

    #pragma unroll
    for (int r = 0; r < 8; r++) {
        int li = r*256 + t;
        int i = li >> 6, p = li & 63;
        sfe[i*68+p] = feat[(size_t)(b*32 + i)*NPT + n0 + p];
    }
    if (t < 64) {
        const float* xr = xyz + (base + t)*3;
        float X = xr[0], Y = xr[1], Z = xr[2];
        sh[t*4+0] = fmaxf(fmaf(g_Wp1f[0], X, fmaf(g_Wp1f[1], Y, fmaf(g_Wp1f[2], Z, g_tp[0]))), 0.f);
        sh[t*4+1] = fmaxf(fmaf(g_Wp1f[3], X, fmaf(g_Wp1f[4], Y, fmaf(g_Wp1f[5], Z, g_tp[1]))), 0.f);
        sh[t*4+2] = fmaxf(fmaf(g_Wp1f[6], X, fmaf(g_Wp1f[7], Y, fmaf(g_Wp1f[8], Z, g_tp[2]))), 0.f);
    }
    __syncthreads();

    int cc = t & 15, pg = t >> 4;
    int cb = 4*cc, pb = 4*pg;

    // ---- GEMM1: f = relu(W1f x + t1); write g_f and sf
    {
        float af[4][4];
        #pragma unroll
        for (int x = 0; x < 4; x++)
            #pragma unroll
            for (int y = 0; y < 4; y++) af[x][y] = 0.f;

        #pragma unroll
        for (int i = 0; i < 32; i++) {
            float4 w  = *(const float4*)&g_W1f[i*64 + cb];
            float4 fv = *(const float4*)&sfe[i*68 + pb];
            float wc[4] = {w.x,w.y,w.z,w.w};
            float fp[4] = {fv.x,fv.y,fv.z,fv.w};
            #pragma unroll
            for (int ch = 0; ch < 4; ch++)
                #pragma unroll
                for (int pp = 0; pp < 4; pp++)
                    af[ch][pp] = fmaf(wc[ch], fp[pp], af[ch][pp]);
        }
        float4 t1v = *(const float4*)&g_t1[cb];
        float tb[4] = {t1v.x, t1v.y, t1v.z, t1v.w};
        #pragma unroll
        for (int ch = 0; ch < 4; ch++)
            #pragma unroll
            for (int pp = 0; pp < 4; pp++) {
                float v = fmaxf(af[ch][pp] + tb[ch], 0.f);
                af[ch][pp] = v;
                sf[(cb+ch)*68 + pb + pp] = v;
            }
        #pragma unroll
        for (int pp = 0; pp < 4; pp++)
            *(float4*)&g_f[(base + pb + pp)*64 + cb] =
                make_float4(af[0][pp], af[1][pp], af[2][pp], af[3][pp]);
    }
    __syncthreads();

    // ---- projections: z=0 QS, z=1 K', z=2 V'
    #pragma unroll
    for (int z = 0; z < 3; z++) {
        const float* W    = (z == 0) ? g_WqT : (z == 1) ? g_WkT : g_WvT;
        const float* bias = (z == 0) ? g_bqv : (z == 1) ? g_bkv : g_bvv;

        float a[4][4];
        #pragma unroll
        for (int x = 0; x < 4; x++)
            #pragma unroll
            for (int y = 0; y < 4; y++) a[x][y] = 0.f;

        #pragma unroll 8
        for (int c = 0; c < 64; c++) {
            float4 w  = *(const float4*)&W[c*64 + cb];
            float4 fv = *(const float4*)&sf[c*68 + pb];
            float wc[4] = {w.x,w.y,w.z,w.w};
            float fp[4] = {fv.x,fv.y,fv.z,fv.w};
            #pragma unroll
            for (int ch = 0; ch < 4; ch++)
                #pragma unroll
                for (int pp = 0; pp < 4; pp++)
                    a[ch][pp] = fmaf(wc[ch], fp[pp], a[ch][pp]);
        }
        float4 bb = *(const float4*)&bias[cb];
        float bvr[4] = {bb.x, bb.y, bb.z, bb.w};

        if (z == 0) {
            #pragma unroll
            for (int pp = 0; pp < 4; pp++) {
                float o[4];
                #pragma unroll
                for (int ch = 0; ch < 4; ch++) {
                    float2 st = *(const float2*)&g_s0t0[(cb+ch)*2];
                    o[ch] = fmaf(st.x, a[ch][pp] + bvr[ch], -st.y);
                }
                *(float4*)&g_q[(base + pb + pp)*64 + cb] =
                    make_float4(o[0], o[1], o[2], o[3]);
            }
        } else {
            float* dst = (z == 1) ? g_kv : (g_kv + 64);
            #pragma unroll
            for (int pp = 0; pp < 4; pp++) {
                float h0 = sh[(pb+pp)*4+0], h1 = sh[(pb+pp)*4+1], h2 = sh[(pb+pp)*4+2];
                float o[4];
                #pragma unroll
                for (int ch = 0; ch < 4; ch++) {
                    float4 wp = *(const float4*)&g_Wp2b[(cb+ch)*4];
                    float pr = fmaf(wp.x, h0, fmaf(wp.y, h1, fmaf(wp.z, h2, wp.w)));
                    float val = a[ch][pp] + bvr[ch] + pr;
                    if (z == 1) val *= g_s0t0[(cb+ch)*2];
                    o[ch] = val;
                }
                *(float4*)&dst[(base + pb + pp)*128 + cb] =
                    make_float4(o[0], o[1], o[2], o[3]);
            }
        }
    }
}

// ---------------- attention core: writes xm (point-major) -------------------
#define WPB 4
__global__ void __launch_bounds__(128) k_attn(const int* __restrict__ nidx)
{
    __shared__ float skv[WPB][16*64];   // K' only: 16 rows x 256B, swizzled
    __shared__ float swt[WPB][132];
    __shared__ float sWw1f[512];
    __shared__ float sWw2[64];
    __shared__ float sAux[16];

    int t = threadIdx.x;
    sWw1f[t]       = g_Ww1f[t];
    sWw1f[128+t]   = g_Ww1f[128+t];
    sWw1f[256+t]   = g_Ww1f[256+t];
    sWw1f[384+t]   = g_Ww1f[384+t];
    if (t < 64)    sWw2[t] = g_Ww2m[t];
    if (t < 8)   { sAux[t] = g_tw1[t]; sAux[8+t] = g_bw2v[t]; }
    __syncthreads();

    int warp = t >> 5, l = t & 31;
    int pid = blockIdx.x * WPB + warp;
    int b   = pid >> 14;
    int n   = pid & 16383;
    size_t rowb  = (size_t)b * NPT;
    size_t pbase = (rowb + n) * 64;

    int k = l & 15, h = l >> 4;
    int c0 = 32 * h;

    const int* nrow = nidx + (size_t)pid*16;
    int myidx = (l < 16) ? __ldg(nrow + l) : 0;

    // cooperative gather of K' via cp.async (no register round-trip)
    float* skvw = skv[warp];
    int i2 = l >> 4, ch16 = l & 15;
    #pragma unroll
    for (int i = 0; i < 8; i++) {
        int row = 2*i + i2;
        int r = __shfl_sync(0xffffffffu, myidx, row);
        const float4* src = (const float4*)(g_kv + (rowb + r)*128) + ch16;
        int pp = ch16 ^ (row & 7);
        unsigned dst = (unsigned)__cvta_generic_to_shared(&skvw[row*64 + pp*4]);
        asm volatile("cp.async.cg.shared.global [%0], [%1], 16;" :: "r"(dst), "l"(src));
    }
    asm volatile("cp.async.commit_group;" ::: "memory");
    asm volatile("cp.async.wait_group 0;" ::: "memory");
    __syncwarp();

    // phase 1: u = lrelu(K' - QS), accumulate Ww1 partials over own 32 channels
    float w1p[8];
    #pragma unroll
    for (int j = 0; j < 8; j++) w1p[j] = 0.f;

    int sw8 = k & 7;
    #pragma unroll
    for (int s = 0; s < 8; s++) {
        int c = c0 + 4*s;
        float4 kk = *(const float4*)&skvw[k*64 + ((h*8 + s) ^ sw8)*4];
        float4 qs = __ldg((const float4*)(g_q + pbase + c));
        float kr[4] = {kk.x,kk.y,kk.z,kk.w};
        float qr[4] = {qs.x,qs.y,qs.z,qs.w};
        #pragma unroll
        for (int e = 0; e < 4; e++) {
            int ch = c + e;
            float u = lrelu(kr[e] - qr[e]);
            float4 wA = *(const float4*)(sWw1f + ch*8);
            float4 wB = *(const float4*)(sWw1f + ch*8 + 4);
            w1p[0] = fmaf(wA.x, u, w1p[0]); w1p[1] = fmaf(wA.y, u, w1p[1]);
            w1p[2] = fmaf(wA.z, u, w1p[2]); w1p[3] = fmaf(wA.w, u, w1p[3]);
            w1p[4] = fmaf(wB.x, u, w1p[4]); w1p[5] = fmaf(wB.y, u, w1p[5]);
            w1p[6] = fmaf(wB.z, u, w1p[6]); w1p[7] = fmaf(wB.w, u, w1p[7]);
        }
    }

    #pragma unroll
    for (int j = 0; j < 8; j++)
        w1p[j] += __shfl_xor_sync(0xffffffffu, w1p[j], 16);

    // tw1/bw2 as vector loads; Ww2 rows hoisted into registers
    float4 tA = *(const float4*)&sAux[0];
    float4 tB = *(const float4*)&sAux[4];
    float tw[8] = {tA.x,tA.y,tA.z,tA.w,tB.x,tB.y,tB.z,tB.w};
    float w1v[8];
    #pragma unroll
    for (int j = 0; j < 8; j++) w1v[j] = fmaxf(w1p[j] + tw[j], 0.f);

    float2 bw = *(const float2*)&sAux[8 + 4*h + 0];
    float2 bw2_ = *(const float2*)&sAux[8 + 4*h + 2];
    float bwr[4] = {bw.x, bw.y, bw2_.x, bw2_.y};

    float wt[4];
    #pragma unroll
    for (int jj = 0; jj < 4; jj++) {
        int j = 4*h + jj;
        float4 rA = *(const float4*)&sWw2[j*8];
        float4 rB = *(const float4*)&sWw2[j*8 + 4];
        float a = bwr[jj];
        a = fmaf(rA.x, w1v[0], a); a = fmaf(rA.y, w1v[1], a);
        a = fmaf(rA.z, w1v[2], a); a = fmaf(rA.w, w1v[3], a);
        a = fmaf(rB.x, w1v[4], a); a = fmaf(rB.y, w1v[5], a);
        a = fmaf(rB.z, w1v[6], a); a = fmaf(rB.w, w1v[7], a);
        wt[jj] = a;
    }
    *(float4*)&swt[warp][k*8 + 4*h] = make_float4(wt[0], wt[1], wt[2], wt[3]);
    __syncwarp();

    // softmax over K
    {
        int j = l >> 2, kq = l & 3;
        float v0 = swt[warp][(4*kq+0)*8 + j];
        float v1 = swt[warp][(4*kq+1)*8 + j];
        float v2 = swt[warp][(4*kq+2)*8 + j];
        float v3 = swt[warp][(4*kq+3)*8 + j];
        float mx = fmaxf(fmaxf(v0, v1), fmaxf(v2, v3));
        mx = fmaxf(mx, __shfl_xor_sync(0xffffffffu, mx, 1));
        mx = fmaxf(mx, __shfl_xor_sync(0xffffffffu, mx, 2));
        float e0 = __expf(v0 - mx), e1 = __expf(v1 - mx);
        float e2 = __expf(v2 - mx), e3 = __expf(v3 - mx);
        float sm = e0 + e1 + e2 + e3;
        sm += __shfl_xor_sync(0xffffffffu, sm, 1);
        sm += __shfl_xor_sync(0xffffffffu, sm, 2);
        float inv = __fdividef(1.f, sm);
        swt[warp][(4*kq+0)*8 + j] = e0 * inv;
        swt[warp][(4*kq+1)*8 + j] = e1 * inv;
        swt[warp][(4*kq+2)*8 + j] = e2 * inv;
        swt[warp][(4*kq+3)*8 + j] = e3 * inv;
    }
    __syncwarp();

    // phase 3: lane owns channels 2l, 2l+1; V' read from global (L2-hot)
    int cc0 = 2*l;
    int j0 = cc0 & 7;
    float acc0 = 0.f, acc1 = 0.f;
    #pragma unroll
    for (int kk2 = 0; kk2 < 16; kk2++) {
        float2 wv = *(const float2*)&swt[warp][kk2*8 + j0];
        int r = __shfl_sync(0xffffffffu, myidx, kk2);
        float2 vv = __ldg((const float2*)(g_kv + (rowb + r)*128 + 64 + cc0));
        acc0 = fmaf(wv.x, vv.x, acc0);
        acc1 = fmaf(wv.y, vv.y, acc1);
    }

    float4 sm4 = *(const float4*)(g_smt + 4*l);
    float xa = lrelu(fmaf(sm4.x, acc0, sm4.y));
    float xb = lrelu(fmaf(sm4.z, acc1, sm4.w));
    *(float2*)&g_xm[pbase + cc0] = make_float2(xa, xb);
}

// ---------------- conv2 + residual + lrelu, channel-split GEMM --------------
// blockIdx.z selects 32 output channels; grid doubles -> ~86% occ ceiling
__global__ void __launch_bounds__(256) k_out(float* __restrict__ out)
{
    __shared__ float sbuf[64*68];
    int t  = threadIdx.x;
    int b  = blockIdx.y;
    int n0 = blockIdx.x * 64;
    int z  = blockIdx.z;              // channel half
    int zc = z * 32;
    size_t base = (size_t)b*NPT + n0;

    // stage full xm tile transposed: sbuf[c][p]
    int p = t & 63, chunk = t >> 6;
    #pragma unroll
    for (int j = 0; j < 4; j++) {
        int ch = chunk*16 + 4*j;
        float4 v = *(const float4*)&g_xm[(base + p)*64 + ch];
        sbuf[(ch+0)*68+p] = v.x;
        sbuf[(ch+1)*68+p] = v.y;
        sbuf[(ch+2)*68+p] = v.z;
        sbuf[(ch+3)*68+p] = v.w;
    }
    __syncthreads();

    int cc = t & 15, pg = t >> 4;   // 16 ch-pairs x 16 point-quads
    int cb = 2*cc, pb = 4*pg;       // local out-ch pair, point quad

    float a0[4], a1[4];
    #pragma unroll
    for (int pp = 0; pp < 4; pp++) { a0[pp] = 0.f; a1[pp] = 0.f; }

    #pragma unroll 8
    for (int c = 0; c < 64; c++) {
        float4 xv = *(const float4*)&sbuf[c*68 + pb];
        float2 w  = *(const float2*)&g_W2T[c*64 + zc + cb];
        a0[0] = fmaf(w.x, xv.x, a0[0]); a1[0] = fmaf(w.y, xv.x, a1[0]);
        a0[1] = fmaf(w.x, xv.y, a0[1]); a1[1] = fmaf(w.y, xv.y, a1[1]);
        a0[2] = fmaf(w.x, xv.z, a0[2]); a1[2] = fmaf(w.y, xv.z, a1[2]);
        a0[3] = fmaf(w.x, xv.w, a0[3]); a1[3] = fmaf(w.y, xv.w, a1[3]);
    }
    __syncthreads();   // done reading sbuf, reuse rows [0,32) as output stage

    float2 t2v = *(const float2*)&g_t2[zc + cb];
    #pragma unroll
    for (int pp = 0; pp < 4; pp++) {
        float2 fv = *(const float2*)&g_f[(base + pb + pp)*64 + zc + cb];
        sbuf[(cb+0)*68 + pb + pp] = lrelu(a0[pp] + t2v.x + fv.x);
        sbuf[(cb+1)*68 + pb + pp] = lrelu(a1[pp] + t2v.y + fv.y);
    }
    __syncthreads();

    // coalesced channel-major store: 32 channels x 64 points = 8 floats/thread
    int cO = t >> 3, q = t & 7;     // local channel 0..31, point chunk 0..7
    #pragma unroll
    for (int i = 0; i < 2; i++) {
        float4 vq = *(const float4*)&sbuf[cO*68 + q*8 + 4*i];
        *(float4*)&out[((size_t)(b*64 + zc + cO))*NPT + n0 + q*8 + 4*i] = vq;
    }
}

extern "C" void kernel_launch(void* const* d_in, const int* in_sizes, int n_in,
                              void* d_out, int out_size)
{
    const float* feature = (const float*)d_in[0];
    const float* xyz     = (const float*)d_in[1];
    const float* W1      = (const float*)d_in[2];
    const float* bn1     = (const float*)d_in[3];
    const float* Wq      = (const float*)d_in[4];
    const float* bq      = (const float*)d_in[5];
    const float* Wk      = (const float*)d_in[6];
    const float* bk      = (const float*)d_in[7];
    const float* Wv      = (const float*)d_in[8];
    const float* bv      = (const float*)d_in[9];
    const float* Wp1     = (const float*)d_in[10];
    const float* bnp1    = (const float*)d_in[11];
    const float* Wp2     = (const float*)d_in[12];
    const float* bp2     = (const float*)d_in[13];
    const float* bnw0    = (const float*)d_in[14];
    const float* Ww1     = (const float*)d_in[15];
    const float* bnw1    = (const float*)d_in[16];
    const float* Ww2     = (const float*)d_in[17];
    const float* bw2     = (const float*)d_in[18];
    const float* bn_mid  = (const float*)d_in[19];
    const float* W2      = (const float*)d_in[20];
    const float* bn2     = (const float*)d_in[21];
    const int*   nidx    = (const int*)d_in[22];
    float* out = (float*)d_out;

    k_prep<<<64, 64>>>(W1, bn1, Wq, bq, Wk, bk, Wv, bv, Wp1, bnp1, Wp2, bp2,
                       bnw0, Ww1, bnw1, Ww2, bw2, bn_mid, W2, bn2);
    dim3 gf(NPT/64, BB);
    k_proj<<<gf, 256>>>(feature, xyz);
    k_attn<<<(BB*NPT)/WPB, 128>>>(nidx);
    dim3 go(NPT/64, BB, 2);
    k_out<<<go, 256>>>(out);
}

// round 15
// speedup vs baseline: 1.0246x; 1.0239x over previous
#include <cuda_runtime.h>

#define NPT 16384
#define BB  2

__device__ float g_f [BB*NPT*64];
__device__ float g_q [BB*NPT*64];     // QS = s0*q - t0
__device__ float g_kv[BB*NPT*128];    // [row][0:64]=s0*(k+pr), [64:128]=v+pr
__device__ float g_xm[BB*NPT*64];

__device__ float g_W1f[32*64];
__device__ float g_t1[64];
__device__ float g_WqT[64*64], g_WkT[64*64], g_WvT[64*64];
__device__ float g_bqv[64], g_bkv[64], g_bvv[64];
__device__ float g_Wp1f[9], g_tp[3];
__device__ float g_Wp2b[64*4];
__device__ float g_s0t0[64*2];
__device__ float g_Ww1f[64*8];
__device__ float g_tw1[8], g_Ww2m[64], g_bw2v[8];
__device__ float g_smt[64*2];
__device__ float g_W2T[64*64], g_t2[64];

__device__ __forceinline__ float lrelu(float x) { return fmaxf(x, 0.2f*x); }

// ---------------- prep: 64 blocks x 64 threads ------------------------------
__global__ void k_prep(const float* __restrict__ W1,  const float* __restrict__ bn1,
                       const float* __restrict__ Wq,  const float* __restrict__ bq,
                       const float* __restrict__ Wk,  const float* __restrict__ bk,
                       const float* __restrict__ Wv,  const float* __restrict__ bv,
                       const float* __restrict__ Wp1, const float* __restrict__ bnp1,
                       const float* __restrict__ Wp2, const float* __restrict__ bp2,
                       const float* __restrict__ bnw0,const float* __restrict__ Ww1,
                       const float* __restrict__ bnw1,const float* __restrict__ Ww2,
                       const float* __restrict__ bw2, const float* __restrict__ bn_mid,
                       const float* __restrict__ W2,  const float* __restrict__ bn2)
{
    int c = blockIdx.x;   // 0..63 output channel
    int i = threadIdx.x;  // 0..63 input channel
    float s1 = bn1[c] * rsqrtf(bn1[192+c] + 1e-5f);
    float s2 = bn2[c] * rsqrtf(bn2[192+c] + 1e-5f);
    if (i < 32) g_W1f[i*64+c] = W1[c*32+i]*s1;
    g_WqT[i*64+c] = Wq[c*64+i];
    g_WkT[i*64+c] = Wk[c*64+i];
    g_WvT[i*64+c] = Wv[c*64+i];
    g_W2T[i*64+c] = W2[c*64+i]*s2;
    if (i < 8) {
        float sw = bnw1[i] * rsqrtf(bnw1[24+i] + 1e-5f);
        g_Ww1f[c*8+i] = Ww1[i*64+c]*sw;
    }
    if (i == 0) {
        g_t1[c] = bn1[64+c] - bn1[128+c]*s1;
        g_bqv[c] = bq[c]; g_bkv[c] = bk[c]; g_bvv[c] = bv[c];
        g_Wp2b[c*4+0] = Wp2[c*3+0];
        g_Wp2b[c*4+1] = Wp2[c*3+1];
        g_Wp2b[c*4+2] = Wp2[c*3+2];
        g_Wp2b[c*4+3] = bp2[c];
        float s0 = bnw0[c] * rsqrtf(bnw0[192+c] + 1e-5f);
        g_s0t0[c*2+0] = s0;
        g_s0t0[c*2+1] = bnw0[64+c] - bnw0[128+c]*s0;
        float sm = bn_mid[c] * rsqrtf(bn_mid[192+c] + 1e-5f);
        g_smt[c*2+0] = sm;
        g_smt[c*2+1] = bn_mid[64+c] - bn_mid[128+c]*sm;
        g_t2[c] = bn2[64+c] - bn2[128+c]*s2;
    }
    if (c == 0) {
        if (i < 3) {
            float sp = bnp1[i] * rsqrtf(bnp1[9+i] + 1e-5f);
            g_Wp1f[i*3+0] = Wp1[i*3+0]*sp;
            g_Wp1f[i*3+1] = Wp1[i*3+1]*sp;
            g_Wp1f[i*3+2] = Wp1[i*3+2]*sp;
            g_tp[i] = bnp1[3+i] - bnp1[6+i]*sp;
        }
        if (i < 8) {
            float sw = bnw1[i] * rsqrtf(bnw1[24+i] + 1e-5f);
            g_tw1[i]  = bnw1[8+i] - bnw1[16+i]*sw;
            g_bw2v[i] = bw2[i];
        }
        g_Ww2m[i] = Ww2[i];
    }
}

// ---------------- fused projections: f, QS, K', V' (scalar float4 GEMMs) ----
__global__ void __launch_bounds__(256) k_proj(const float* __restrict__ feat,
                                              const float* __restrict__ xyz)
{
    __shared__ float sfe[32*68];
    __shared__ float sf [64*68];   // f tile, [c][p]
    __shared__ float sh [64*4];    // pos-MLP hidden per point
    int t  = threadIdx.x;
    int b  = blockIdx.y;
    int n0 = blockIdx.x * 64;
    size_t base = (size_t)b*NPT + n0;

    #pragma unroll
    for (int r = 0; r < 8; r++) {
        int li = r*256 + t;
        int i = li >> 6, p = li & 63;
        sfe[i*68+p] = feat[(size_t)(b*32 + i)*NPT + n0 + p];
    }
    if (t < 64) {
        const float* xr = xyz + (base + t)*3;
        float X = xr[0], Y = xr[1], Z = xr[2];
        sh[t*4+0] = fmaxf(fmaf(g_Wp1f[0], X, fmaf(g_Wp1f[1], Y, fmaf(g_Wp1f[2], Z, g_tp[0]))), 0.f);
        sh[t*4+1] = fmaxf(fmaf(g_Wp1f[3], X, fmaf(g_Wp1f[4], Y, fmaf(g_Wp1f[5], Z, g_tp[1]))), 0.f);
        sh[t*4+2] = fmaxf(fmaf(g_Wp1f[6], X, fmaf(g_Wp1f[7], Y, fmaf(g_Wp1f[8], Z, g_tp[2]))), 0.f);
    }
    __syncthreads();

    int cc = t & 15, pg = t >> 4;
    int cb = 4*cc, pb = 4*pg;

    // ---- GEMM1: f = relu(W1f x + t1); write g_f and sf
    {
        float af[4][4];
        #pragma unroll
        for (int x = 0; x < 4; x++)
            #pragma unroll
            for (int y = 0; y < 4; y++) af[x][y] = 0.f;

        #pragma unroll
        for (int i = 0; i < 32; i++) {
            float4 w  = *(const float4*)&g_W1f[i*64 + cb];
            float4 fv = *(const float4*)&sfe[i*68 + pb];
            float wc[4] = {w.x,w.y,w.z,w.w};
            float fp[4] = {fv.x,fv.y,fv.z,fv.w};
            #pragma unroll
            for (int ch = 0; ch < 4; ch++)
                #pragma unroll
                for (int pp = 0; pp < 4; pp++)
                    af[ch][pp] = fmaf(wc[ch], fp[pp], af[ch][pp]);
        }
        float4 t1v = *(const float4*)&g_t1[cb];
        float tb[4] = {t1v.x, t1v.y, t1v.z, t1v.w};
        #pragma unroll
        for (int ch = 0; ch < 4; ch++)
            #pragma unroll
            for (int pp = 0; pp < 4; pp++) {
                float v = fmaxf(af[ch][pp] + tb[ch], 0.f);
                af[ch][pp] = v;
                sf[(cb+ch)*68 + pb + pp] = v;
            }
        #pragma unroll
        for (int pp = 0; pp < 4; pp++)
            *(float4*)&g_f[(base + pb + pp)*64 + cb] =
                make_float4(af[0][pp], af[1][pp], af[2][pp], af[3][pp]);
    }
    __syncthreads();

    // ---- projections: z=0 QS, z=1 K', z=2 V'
    #pragma unroll
    for (int z = 0; z < 3; z++) {
        const float* W    = (z == 0) ? g_WqT : (z == 1) ? g_WkT : g_WvT;
        const float* bias = (z == 0) ? g_bqv : (z == 1) ? g_bkv : g_bvv;

        float a[4][4];
        #pragma unroll
        for (int x = 0; x < 4; x++)
            #pragma unroll
            for (int y = 0; y < 4; y++) a[x][y] = 0.f;

        #pragma unroll 8
        for (int c = 0; c < 64; c++) {
            float4 w  = *(const float4*)&W[c*64 + cb];
            float4 fv = *(const float4*)&sf[c*68 + pb];
            float wc[4] = {w.x,w.y,w.z,w.w};
            float fp[4] = {fv.x,fv.y,fv.z,fv.w};
            #pragma unroll
            for (int ch = 0; ch < 4; ch++)
                #pragma unroll
                for (int pp = 0; pp < 4; pp++)
                    a[ch][pp] = fmaf(wc[ch], fp[pp], a[ch][pp]);
        }
        float4 bb = *(const float4*)&bias[cb];
        float bvr[4] = {bb.x, bb.y, bb.z, bb.w};

        if (z == 0) {
            #pragma unroll
            for (int pp = 0; pp < 4; pp++) {
                float o[4];
                #pragma unroll
                for (int ch = 0; ch < 4; ch++) {
                    float2 st = *(const float2*)&g_s0t0[(cb+ch)*2];
                    o[ch] = fmaf(st.x, a[ch][pp] + bvr[ch], -st.y);
                }
                *(float4*)&g_q[(base + pb + pp)*64 + cb] =
                    make_float4(o[0], o[1], o[2], o[3]);
            }
        } else {
            float* dst = (z == 1) ? g_kv : (g_kv + 64);
            #pragma unroll
            for (int pp = 0; pp < 4; pp++) {
                float h0 = sh[(pb+pp)*4+0], h1 = sh[(pb+pp)*4+1], h2 = sh[(pb+pp)*4+2];
                float o[4];
                #pragma unroll
                for (int ch = 0; ch < 4; ch++) {
                    float4 wp = *(const float4*)&g_Wp2b[(cb+ch)*4];
                    float pr = fmaf(wp.x, h0, fmaf(wp.y, h1, fmaf(wp.z, h2, wp.w)));
                    float val = a[ch][pp] + bvr[ch] + pr;
                    if (z == 1) val *= g_s0t0[(cb+ch)*2];
                    o[ch] = val;
                }
                *(float4*)&dst[(base + pb + pp)*128 + cb] =
                    make_float4(o[0], o[1], o[2], o[3]);
            }
        }
    }
}

// ---------------- attention core: K'+V' prefetched via cp.async -------------
#define WPB 4
__global__ void __launch_bounds__(128) k_attn(const int* __restrict__ nidx)
{
    __shared__ float skv[WPB][32*64];   // rows 0-15: K', rows 16-31: V' (swizzled)
    __shared__ float swt[WPB][132];
    __shared__ float sWw1f[512];
    __shared__ float sWw2[64];
    __shared__ float sAux[16];

    int t = threadIdx.x;
    sWw1f[t]       = g_Ww1f[t];
    sWw1f[128+t]   = g_Ww1f[128+t];
    sWw1f[256+t]   = g_Ww1f[256+t];
    sWw1f[384+t]   = g_Ww1f[384+t];
    if (t < 64)    sWw2[t] = g_Ww2m[t];
    if (t < 8)   { sAux[t] = g_tw1[t]; sAux[8+t] = g_bw2v[t]; }
    __syncthreads();

    int warp = t >> 5, l = t & 31;
    int pid = blockIdx.x * WPB + warp;
    int b   = pid >> 14;
    int n   = pid & 16383;
    size_t rowb  = (size_t)b * NPT;
    size_t pbase = (rowb + n) * 64;

    int k = l & 15, h = l >> 4;
    int c0 = 32 * h;

    const int* nrow = nidx + (size_t)pid*16;
    int myidx = (l < 16) ? __ldg(nrow + l) : 0;

    float* skvw = skv[warp];
    int i2 = l >> 4, ch16 = l & 15;

    // group 1: K' rows (needed first)
    #pragma unroll
    for (int i = 0; i < 8; i++) {
        int row = 2*i + i2;
        int r = __shfl_sync(0xffffffffu, myidx, row);
        const float4* src = (const float4*)(g_kv + (rowb + r)*128) + ch16;
        int pp = ch16 ^ (row & 7);
        unsigned dst = (unsigned)__cvta_generic_to_shared(&skvw[row*64 + pp*4]);
        asm volatile("cp.async.cg.shared.global [%0], [%1], 16;" :: "r"(dst), "l"(src));
    }
    asm volatile("cp.async.commit_group;" ::: "memory");
    // group 2: V' rows (needed after softmax; overlaps phase 1)
    #pragma unroll
    for (int i = 0; i < 8; i++) {
        int row = 2*i + i2;
        int r = __shfl_sync(0xffffffffu, myidx, row);
        const float4* src = (const float4*)(g_kv + (rowb + r)*128 + 64) + ch16;
        int pp = ch16 ^ (row & 7);
        unsigned dst = (unsigned)__cvta_generic_to_shared(&skvw[(16+row)*64 + pp*4]);
        asm volatile("cp.async.cg.shared.global [%0], [%1], 16;" :: "r"(dst), "l"(src));
    }
    asm volatile("cp.async.commit_group;" ::: "memory");
    asm volatile("cp.async.wait_group 1;" ::: "memory");   // K' ready, V' in flight
    __syncwarp();

    // phase 1: u = lrelu(K' - QS), accumulate Ww1 partials over own 32 channels
    float w1p[8];
    #pragma unroll
    for (int j = 0; j < 8; j++) w1p[j] = 0.f;

    int sw8 = k & 7;
    #pragma unroll
    for (int s = 0; s < 8; s++) {
        int c = c0 + 4*s;
        float4 kk = *(const float4*)&skvw[k*64 + ((h*8 + s) ^ sw8)*4];
        float4 qs = __ldg((const float4*)(g_q + pbase + c));
        float kr[4] = {kk.x,kk.y,kk.z,kk.w};
        float qr[4] = {qs.x,qs.y,qs.z,qs.w};
        #pragma unroll
        for (int e = 0; e < 4; e++) {
            int ch = c + e;
            float u = lrelu(kr[e] - qr[e]);
            float4 wA = *(const float4*)(sWw1f + ch*8);
            float4 wB = *(const float4*)(sWw1f + ch*8 + 4);
            w1p[0] = fmaf(wA.x, u, w1p[0]); w1p[1] = fmaf(wA.y, u, w1p[1]);
            w1p[2] = fmaf(wA.z, u, w1p[2]); w1p[3] = fmaf(wA.w, u, w1p[3]);
            w1p[4] = fmaf(wB.x, u, w1p[4]); w1p[5] = fmaf(wB.y, u, w1p[5]);
            w1p[6] = fmaf(wB.z, u, w1p[6]); w1p[7] = fmaf(wB.w, u, w1p[7]);
        }
    }

    #pragma unroll
    for (int j = 0; j < 8; j++)
        w1p[j] += __shfl_xor_sync(0xffffffffu, w1p[j], 16);

    float4 tA = *(const float4*)&sAux[0];
    float4 tB = *(const float4*)&sAux[4];
    float tw[8] = {tA.x,tA.y,tA.z,tA.w,tB.x,tB.y,tB.z,tB.w};
    float w1v[8];
    #pragma unroll
    for (int j = 0; j < 8; j++) w1v[j] = fmaxf(w1p[j] + tw[j], 0.f);

    float2 bw = *(const float2*)&sAux[8 + 4*h + 0];
    float2 bw2_ = *(const float2*)&sAux[8 + 4*h + 2];
    float bwr[4] = {bw.x, bw.y, bw2_.x, bw2_.y};

    float wt[4];
    #pragma unroll
    for (int jj = 0; jj < 4; jj++) {
        int j = 4*h + jj;
        float4 rA = *(const float4*)&sWw2[j*8];
        float4 rB = *(const float4*)&sWw2[j*8 + 4];
        float a = bwr[jj];
        a = fmaf(rA.x, w1v[0], a); a = fmaf(rA.y, w1v[1], a);
        a = fmaf(rA.z, w1v[2], a); a = fmaf(rA.w, w1v[3], a);
        a = fmaf(rB.x, w1v[4], a); a = fmaf(rB.y, w1v[5], a);
        a = fmaf(rB.z, w1v[6], a); a = fmaf(rB.w, w1v[7], a);
        wt[jj] = a;
    }
    *(float4*)&swt[warp][k*8 + 4*h] = make_float4(wt[0], wt[1], wt[2], wt[3]);
    __syncwarp();

    // softmax over K
    {
        int j = l >> 2, kq = l & 3;
        float v0 = swt[warp][(4*kq+0)*8 + j];
        float v1 = swt[warp][(4*kq+1)*8 + j];
        float v2 = swt[warp][(4*kq+2)*8 + j];
        float v3 = swt[warp][(4*kq+3)*8 + j];
        float mx = fmaxf(fmaxf(v0, v1), fmaxf(v2, v3));
        mx = fmaxf(mx, __shfl_xor_sync(0xffffffffu, mx, 1));
        mx = fmaxf(mx, __shfl_xor_sync(0xffffffffu, mx, 2));
        float e0 = __expf(v0 - mx), e1 = __expf(v1 - mx);
        float e2 = __expf(v2 - mx), e3 = __expf(v3 - mx);
        float sm = e0 + e1 + e2 + e3;
        sm += __shfl_xor_sync(0xffffffffu, sm, 1);
        sm += __shfl_xor_sync(0xffffffffu, sm, 2);
        float inv = __fdividef(1.f, sm);
        swt[warp][(4*kq+0)*8 + j] = e0 * inv;
        swt[warp][(4*kq+1)*8 + j] = e1 * inv;
        swt[warp][(4*kq+2)*8 + j] = e2 * inv;
        swt[warp][(4*kq+3)*8 + j] = e3 * inv;
    }
    asm volatile("cp.async.wait_group 0;" ::: "memory");   // V' ready
    __syncwarp();

    // phase 3: lane owns channels 2l, 2l+1; V' from shared (swizzled)
    int cc0 = 2*l;
    int j0 = cc0 & 7;
    int chk = l >> 1;                 // 16B chunk holding cc0 within a row
    int sub = cc0 & 3;
    float acc0 = 0.f, acc1 = 0.f;
    #pragma unroll
    for (int kk2 = 0; kk2 < 16; kk2++) {
        float2 wv = *(const float2*)&swt[warp][kk2*8 + j0];
        int pos = chk ^ (kk2 & 7);
        float2 vv = *(const float2*)&skvw[(16+kk2)*64 + pos*4 + sub];
        acc0 = fmaf(wv.x, vv.x, acc0);
        acc1 = fmaf(wv.y, vv.y, acc1);
    }

    float4 sm4 = *(const float4*)(g_smt + 4*l);
    float xa = lrelu(fmaf(sm4.x, acc0, sm4.y));
    float xb = lrelu(fmaf(sm4.z, acc1, sm4.w));
    *(float2*)&g_xm[pbase + cc0] = make_float2(xa, xb);
}

// ---------------- conv2 + residual + lrelu, tiled GEMM (R8 version) ---------
__global__ void __launch_bounds__(256) k_out(float* __restrict__ out)
{
    __shared__ float sbuf[64*68];
    int t  = threadIdx.x;
    int b  = blockIdx.y;
    int n0 = blockIdx.x * 64;
    size_t base = (size_t)b*NPT + n0;

    int p = t & 63, chunk = t >> 6;
    #pragma unroll
    for (int j = 0; j < 4; j++) {
        int ch = chunk*16 + 4*j;
        float4 v = *(const float4*)&g_xm[(base + p)*64 + ch];
        sbuf[(ch+0)*68+p] = v.x;
        sbuf[(ch+1)*68+p] = v.y;
        sbuf[(ch+2)*68+p] = v.z;
        sbuf[(ch+3)*68+p] = v.w;
    }
    __syncthreads();

    int cc = t & 15, pg = t >> 4;
    int cb = 4*cc, pb = 4*pg;

    float a[4][4];
    #pragma unroll
    for (int x = 0; x < 4; x++)
        #pragma unroll
        for (int y = 0; y < 4; y++) a[x][y] = 0.f;

    #pragma unroll 8
    for (int c = 0; c < 64; c++) {
        float4 w  = *(const float4*)&g_W2T[c*64 + cb];
        float4 xv = *(const float4*)&sbuf[c*68 + pb];
        float wc[4] = {w.x,w.y,w.z,w.w};
        float xp[4] = {xv.x,xv.y,xv.z,xv.w};
        #pragma unroll
        for (int ch = 0; ch < 4; ch++)
            #pragma unroll
            for (int pp = 0; pp < 4; pp++)
                a[ch][pp] = fmaf(wc[ch], xp[pp], a[ch][pp]);
    }
    __syncthreads();   // done reading sbuf, reuse as output stage

    float4 t2v = *(const float4*)&g_t2[cb];
    float tb[4] = {t2v.x, t2v.y, t2v.z, t2v.w};
    #pragma unroll
    for (int pp = 0; pp < 4; pp++) {
        float4 fv = *(const float4*)&g_f[(base + pb + pp)*64 + cb];
        float fr[4] = {fv.x, fv.y, fv.z, fv.w};
        #pragma unroll
        for (int ch = 0; ch < 4; ch++)
            sbuf[(cb+ch)*68 + pb + pp] = lrelu(a[ch][pp] + tb[ch] + fr[ch]);
    }
    __syncthreads();

    int cO = t >> 2, q = t & 3;
    #pragma unroll
    for (int i = 0; i < 4; i++) {
        float4 vq = *(const float4*)&sbuf[cO*68 + q*16 + 4*i];
        *(float4*)&out[((size_t)(b*64 + cO))*NPT + n0 + q*16 + 4*i] = vq;
    }
}

extern "C" void kernel_launch(void* const* d_in, const int* in_sizes, int n_in,
                              void* d_out, int out_size)
{
    const float* feature = (const float*)d_in[0];
    const float* xyz     = (const float*)d_in[1];
    const float* W1      = (const float*)d_in[2];
    const float* bn1     = (const float*)d_in[3];
    const float* Wq      = (const float*)d_in[4];
    const float* bq      = (const float*)d_in[5];
    const float* Wk      = (const float*)d_in[6];
    const float* bk      = (const float*)d_in[7];
    const float* Wv      = (const float*)d_in[8];
    const float* bv      = (const float*)d_in[9];
    const float* Wp1     = (const float*)d_in[10];
    const float* bnp1    = (const float*)d_in[11];
    const float* Wp2     = (const float*)d_in[12];
    const float* bp2     = (const float*)d_in[13];
    const float* bnw0    = (const float*)d_in[14];
    const float* Ww1     = (const float*)d_in[15];
    const float* bnw1    = (const float*)d_in[16];
    const float* Ww2     = (const float*)d_in[17];
    const float* bw2     = (const float*)d_in[18];
    const float* bn_mid  = (const float*)d_in[19];
    const float* W2      = (const float*)d_in[20];
    const float* bn2     = (const float*)d_in[21];
    const int*   nidx    = (const int*)d_in[22];
    float* out = (float*)d_out;

    k_prep<<<64, 64>>>(W1, bn1, Wq, bq, Wk, bk, Wv, bv, Wp1, bnp1, Wp2, bp2,
                       bnw0, Ww1, bnw1, Ww2, bw2, bn_mid, W2, bn2);
    dim3 gf(NPT/64, BB);
    k_proj<<<gf, 256>>>(feature, xyz);
    k_attn<<<(BB*NPT)/WPB, 128>>>(nidx);
    k_out<<<gf, 256>>>(out);
}

// round 16
// speedup vs baseline: 1.0937x; 1.0674x over previous
#include <cuda_runtime.h>

#define NPT 16384
#define BB  2

__device__ float g_f [BB*NPT*64];
__device__ float g_q [BB*NPT*64];     // QS = s0*q - t0
__device__ float g_kv[BB*NPT*128];    // [row][0:64]=s0*(k+pr), [64:128]=v+pr
__device__ float g_xm[BB*NPT*64];

__device__ float g_W1f[32*64];
__device__ float g_t1[64];
__device__ float g_WqT[64*64], g_WkT[64*64], g_WvT[64*64];
__device__ float g_bqv[64], g_bkv[64], g_bvv[64];
__device__ float g_Wp1f[9], g_tp[3];
__device__ float g_Wp2b[64*4];
__device__ float g_s0t0[64*2];
__device__ float g_Ww1f[64*8];
__device__ float g_tw1[8], g_Ww2m[64], g_bw2v[8];
__device__ float g_smt[64*2];
__device__ float g_W2T[64*64], g_t2[64];

__device__ __forceinline__ float lrelu(float x) { return fmaxf(x, 0.2f*x); }

// ---------------- prep: 64 blocks x 64 threads ------------------------------
__global__ void k_prep(const float* __restrict__ W1,  const float* __restrict__ bn1,
                       const float* __restrict__ Wq,  const float* __restrict__ bq,
                       const float* __restrict__ Wk,  const float* __restrict__ bk,
                       const float* __restrict__ Wv,  const float* __restrict__ bv,
                       const float* __restrict__ Wp1, const float* __restrict__ bnp1,
                       const float* __restrict__ Wp2, const float* __restrict__ bp2,
                       const float* __restrict__ bnw0,const float* __restrict__ Ww1,
                       const float* __restrict__ bnw1,const float* __restrict__ Ww2,
                       const float* __restrict__ bw2, const float* __restrict__ bn_mid,
                       const float* __restrict__ W2,  const float* __restrict__ bn2)
{
    int c = blockIdx.x;   // 0..63 output channel
    int i = threadIdx.x;  // 0..63 input channel
    float s1 = bn1[c] * rsqrtf(bn1[192+c] + 1e-5f);
    float s2 = bn2[c] * rsqrtf(bn2[192+c] + 1e-5f);
    if (i < 32) g_W1f[i*64+c] = W1[c*32+i]*s1;
    g_WqT[i*64+c] = Wq[c*64+i];
    g_WkT[i*64+c] = Wk[c*64+i];
    g_WvT[i*64+c] = Wv[c*64+i];
    g_W2T[i*64+c] = W2[c*64+i]*s2;
    if (i < 8) {
        float sw = bnw1[i] * rsqrtf(bnw1[24+i] + 1e-5f);
        g_Ww1f[c*8+i] = Ww1[i*64+c]*sw;
    }
    if (i == 0) {
        g_t1[c] = bn1[64+c] - bn1[128+c]*s1;
        g_bqv[c] = bq[c]; g_bkv[c] = bk[c]; g_bvv[c] = bv[c];
        g_Wp2b[c*4+0] = Wp2[c*3+0];
        g_Wp2b[c*4+1] = Wp2[c*3+1];
        g_Wp2b[c*4+2] = Wp2[c*3+2];
        g_Wp2b[c*4+3] = bp2[c];
        float s0 = bnw0[c] * rsqrtf(bnw0[192+c] + 1e-5f);
        g_s0t0[c*2+0] = s0;
        g_s0t0[c*2+1] = bnw0[64+c] - bnw0[128+c]*s0;
        float sm = bn_mid[c] * rsqrtf(bn_mid[192+c] + 1e-5f);
        g_smt[c*2+0] = sm;
        g_smt[c*2+1] = bn_mid[64+c] - bn_mid[128+c]*sm;
        g_t2[c] = bn2[64+c] - bn2[128+c]*s2;
    }
    if (c == 0) {
        if (i < 3) {
            float sp = bnp1[i] * rsqrtf(bnp1[9+i] + 1e-5f);
            g_Wp1f[i*3+0] = Wp1[i*3+0]*sp;
            g_Wp1f[i*3+1] = Wp1[i*3+1]*sp;
            g_Wp1f[i*3+2] = Wp1[i*3+2]*sp;
            g_tp[i] = bnp1[3+i] - bnp1[6+i]*sp;
        }
        if (i < 8) {
            float sw = bnw1[i] * rsqrtf(bnw1[24+i] + 1e-5f);
            g_tw1[i]  = bnw1[8+i] - bnw1[16+i]*sw;
            g_bw2v[i] = bw2[i];
        }
        g_Ww2m[i] = Ww2[i];
    }
}

// ---------------- fused projections: f, QS, K', V' (scalar float4 GEMMs) ----
__global__ void __launch_bounds__(256) k_proj(const float* __restrict__ feat,
                                              const float* __restrict__ xyz)
{
    __shared__ float sfe[32*68];
    __shared__ float sf [64*68];
    __shared__ float sh [64*4];
    int t  = threadIdx.x;
    int b  = blockIdx.y;
    int n0 = blockIdx.x * 64;
    size_t base = (size_t)b*NPT + n0;

    #pragma unroll
    for (int r = 0; r < 8; r++) {
        int li = r*256 + t;
        int i = li >> 6, p = li & 63;
        sfe[i*68+p] = feat[(size_t)(b*32 + i)*NPT + n0 + p];
    }
    if (t < 64) {
        const float* xr = xyz + (base + t)*3;
        float X = xr[0], Y = xr[1], Z = xr[2];
        sh[t*4+0] = fmaxf(fmaf(g_Wp1f[0], X, fmaf(g_Wp1f[1], Y, fmaf(g_Wp1f[2], Z, g_tp[0]))), 0.f);
        sh[t*4+1] = fmaxf(fmaf(g_Wp1f[3], X, fmaf(g_Wp1f[4], Y, fmaf(g_Wp1f[5], Z, g_tp[1]))), 0.f);
        sh[t*4+2] = fmaxf(fmaf(g_Wp1f[6], X, fmaf(g_Wp1f[7], Y, fmaf(g_Wp1f[8], Z, g_tp[2]))), 0.f);
    }
    __syncthreads();

    int cc = t & 15, pg = t >> 4;
    int cb = 4*cc, pb = 4*pg;

    {
        float af[4][4];
        #pragma unroll
        for (int x = 0; x < 4; x++)
            #pragma unroll
            for (int y = 0; y < 4; y++) af[x][y] = 0.f;

        #pragma unroll
        for (int i = 0; i < 32; i++) {
            float4 w  = *(const float4*)&g_W1f[i*64 + cb];
            float4 fv = *(const float4*)&sfe[i*68 + pb];
            float wc[4] = {w.x,w.y,w.z,w.w};
            float fp[4] = {fv.x,fv.y,fv.z,fv.w};
            #pragma unroll
            for (int ch = 0; ch < 4; ch++)
                #pragma unroll
                for (int pp = 0; pp < 4; pp++)
                    af[ch][pp] = fmaf(wc[ch], fp[pp], af[ch][pp]);
        }
        float4 t1v = *(const float4*)&g_t1[cb];
        float tb[4] = {t1v.x, t1v.y, t1v.z, t1v.w};
        #pragma unroll
        for (int ch = 0; ch < 4; ch++)
            #pragma unroll
            for (int pp = 0; pp < 4; pp++) {
                float v = fmaxf(af[ch][pp] + tb[ch], 0.f);
                af[ch][pp] = v;
                sf[(cb+ch)*68 + pb + pp] = v;
            }
        #pragma unroll
        for (int pp = 0; pp < 4; pp++)
            *(float4*)&g_f[(base + pb + pp)*64 + cb] =
                make_float4(af[0][pp], af[1][pp], af[2][pp], af[3][pp]);
    }
    __syncthreads();

    #pragma unroll
    for (int z = 0; z < 3; z++) {
        const float* W    = (z == 0) ? g_WqT : (z == 1) ? g_WkT : g_WvT;
        const float* bias = (z == 0) ? g_bqv : (z == 1) ? g_bkv : g_bvv;

        float a[4][4];
        #pragma unroll
        for (int x = 0; x < 4; x++)
            #pragma unroll
            for (int y = 0; y < 4; y++) a[x][y] = 0.f;

        #pragma unroll 8
        for (int c = 0; c < 64; c++) {
            float4 w  = *(const float4*)&W[c*64 + cb];
            float4 fv = *(const float4*)&sf[c*68 + pb];
            float wc[4] = {w.x,w.y,w.z,w.w};
            float fp[4] = {fv.x,fv.y,fv.z,fv.w};
            #pragma unroll
            for (int ch = 0; ch < 4; ch++)
                #pragma unroll
                for (int pp = 0; pp < 4; pp++)
                    a[ch][pp] = fmaf(wc[ch], fp[pp], a[ch][pp]);
        }
        float4 bb = *(const float4*)&bias[cb];
        float bvr[4] = {bb.x, bb.y, bb.z, bb.w};

        if (z == 0) {
            #pragma unroll
            for (int pp = 0; pp < 4; pp++) {
                float o[4];
                #pragma unroll
                for (int ch = 0; ch < 4; ch++) {
                    float2 st = *(const float2*)&g_s0t0[(cb+ch)*2];
                    o[ch] = fmaf(st.x, a[ch][pp] + bvr[ch], -st.y);
                }
                *(float4*)&g_q[(base + pb + pp)*64 + cb] =
                    make_float4(o[0], o[1], o[2], o[3]);
            }
        } else {
            float* dst = (z == 1) ? g_kv : (g_kv + 64);
            #pragma unroll
            for (int pp = 0; pp < 4; pp++) {
                float h0 = sh[(pb+pp)*4+0], h1 = sh[(pb+pp)*4+1], h2 = sh[(pb+pp)*4+2];
                float o[4];
                #pragma unroll
                for (int ch = 0; ch < 4; ch++) {
                    float4 wp = *(const float4*)&g_Wp2b[(cb+ch)*4];
                    float pr = fmaf(wp.x, h0, fmaf(wp.y, h1, fmaf(wp.z, h2, wp.w)));
                    float val = a[ch][pp] + bvr[ch] + pr;
                    if (z == 1) val *= g_s0t0[(cb+ch)*2];
                    o[ch] = val;
                }
                *(float4*)&dst[(base + pb + pp)*128 + cb] =
                    make_float4(o[0], o[1], o[2], o[3]);
            }
        }
    }
}

// ---------------- attention core: 2 points per warp, shared weight loads ----
#define WPB 4
__global__ void __launch_bounds__(128) k_attn(const int* __restrict__ nidx)
{
    __shared__ float skv[WPB][2][16*64];   // K' tile per point slot (swizzled)
    __shared__ float swt[WPB][2][132];
    __shared__ float sWw1f[512];
    __shared__ float sWw2[64];
    __shared__ float sAux[16];

    int t = threadIdx.x;
    sWw1f[t]       = g_Ww1f[t];
    sWw1f[128+t]   = g_Ww1f[128+t];
    sWw1f[256+t]   = g_Ww1f[256+t];
    sWw1f[384+t]   = g_Ww1f[384+t];
    if (t < 64)    sWw2[t] = g_Ww2m[t];
    if (t < 8)   { sAux[t] = g_tw1[t]; sAux[8+t] = g_bw2v[t]; }
    __syncthreads();

    int warp = t >> 5, l = t & 31;
    int pidA = blockIdx.x * (WPB*2) + warp*2;   // even -> A,B same batch
    int b    = pidA >> 14;
    size_t rowb   = (size_t)b * NPT;
    size_t pbaseA = (rowb + (pidA & 16383)) * 64;
    size_t pbaseB = pbaseA + 64;

    int k = l & 15, h = l >> 4;
    int c0 = 32 * h;

    // lanes 0-15: neighbors of A; lanes 16-31: neighbors of B
    int myidx = __ldg(nidx + (size_t)pidA*16 + l);

    float* skvA = skv[warp][0];
    float* skvB = skv[warp][1];
    int i2 = l >> 4, ch16 = l & 15;
    #pragma unroll
    for (int i = 0; i < 8; i++) {
        int row = 2*i + i2;
        int rA = __shfl_sync(0xffffffffu, myidx, row);
        int rB = __shfl_sync(0xffffffffu, myidx, 16 + row);
        int pp = ch16 ^ (row & 7);
        {
            const float4* src = (const float4*)(g_kv + (rowb + rA)*128) + ch16;
            unsigned dst = (unsigned)__cvta_generic_to_shared(&skvA[row*64 + pp*4]);
            asm volatile("cp.async.cg.shared.global [%0], [%1], 16;" :: "r"(dst), "l"(src));
        }
        {
            const float4* src = (const float4*)(g_kv + (rowb + rB)*128) + ch16;
            unsigned dst = (unsigned)__cvta_generic_to_shared(&skvB[row*64 + pp*4]);
            asm volatile("cp.async.cg.shared.global [%0], [%1], 16;" :: "r"(dst), "l"(src));
        }
    }
    asm volatile("cp.async.commit_group;" ::: "memory");
    asm volatile("cp.async.wait_group 0;" ::: "memory");
    __syncwarp();

    // phase 1: both points share each weight load
    float w1A[8], w1B[8];
    #pragma unroll
    for (int j = 0; j < 8; j++) { w1A[j] = 0.f; w1B[j] = 0.f; }

    int sw8 = k & 7;
    #pragma unroll
    for (int s = 0; s < 8; s++) {
        int c = c0 + 4*s;
        int co = ((h*8 + s) ^ sw8)*4;
        float4 kkA = *(const float4*)&skvA[k*64 + co];
        float4 kkB = *(const float4*)&skvB[k*64 + co];
        float4 qsA = __ldg((const float4*)(g_q + pbaseA + c));
        float4 qsB = __ldg((const float4*)(g_q + pbaseB + c));
        float uA[4] = { lrelu(kkA.x-qsA.x), lrelu(kkA.y-qsA.y),
                        lrelu(kkA.z-qsA.z), lrelu(kkA.w-qsA.w) };
        float uB[4] = { lrelu(kkB.x-qsB.x), lrelu(kkB.y-qsB.y),
                        lrelu(kkB.z-qsB.z), lrelu(kkB.w-qsB.w) };
        #pragma unroll
        for (int e = 0; e < 4; e++) {
            int ch = c + e;
            float4 wA = *(const float4*)(sWw1f + ch*8);
            float4 wB = *(const float4*)(sWw1f + ch*8 + 4);
            float ua = uA[e], ub = uB[e];
            w1A[0] = fmaf(wA.x, ua, w1A[0]); w1A[1] = fmaf(wA.y, ua, w1A[1]);
            w1A[2] = fmaf(wA.z, ua, w1A[2]); w1A[3] = fmaf(wA.w, ua, w1A[3]);
            w1A[4] = fmaf(wB.x, ua, w1A[4]); w1A[5] = fmaf(wB.y, ua, w1A[5]);
            w1A[6] = fmaf(wB.z, ua, w1A[6]); w1A[7] = fmaf(wB.w, ua, w1A[7]);
            w1B[0] = fmaf(wA.x, ub, w1B[0]); w1B[1] = fmaf(wA.y, ub, w1B[1]);
            w1B[2] = fmaf(wA.z, ub, w1B[2]); w1B[3] = fmaf(wA.w, ub, w1B[3]);
            w1B[4] = fmaf(wB.x, ub, w1B[4]); w1B[5] = fmaf(wB.y, ub, w1B[5]);
            w1B[6] = fmaf(wB.z, ub, w1B[6]); w1B[7] = fmaf(wB.w, ub, w1B[7]);
        }
    }

    #pragma unroll
    for (int j = 0; j < 8; j++) {
        w1A[j] += __shfl_xor_sync(0xffffffffu, w1A[j], 16);
        w1B[j] += __shfl_xor_sync(0xffffffffu, w1B[j], 16);
    }

    float4 tA4 = *(const float4*)&sAux[0];
    float4 tB4 = *(const float4*)&sAux[4];
    float tw[8] = {tA4.x,tA4.y,tA4.z,tA4.w,tB4.x,tB4.y,tB4.z,tB4.w};
    float2 bwl = *(const float2*)&sAux[8 + 4*h + 0];
    float2 bwh = *(const float2*)&sAux[8 + 4*h + 2];
    float bwr[4] = {bwl.x, bwl.y, bwh.x, bwh.y};

    // Ww2 matvec + store logits, point A then B
    {
        float w1v[8];
        #pragma unroll
        for (int j = 0; j < 8; j++) w1v[j] = fmaxf(w1A[j] + tw[j], 0.f);
        float wt[4];
        #pragma unroll
        for (int jj = 0; jj < 4; jj++) {
            int j = 4*h + jj;
            float4 rA = *(const float4*)&sWw2[j*8];
            float4 rB = *(const float4*)&sWw2[j*8 + 4];
            float a = bwr[jj];
            a = fmaf(rA.x, w1v[0], a); a = fmaf(rA.y, w1v[1], a);
            a = fmaf(rA.z, w1v[2], a); a = fmaf(rA.w, w1v[3], a);
            a = fmaf(rB.x, w1v[4], a); a = fmaf(rB.y, w1v[5], a);
            a = fmaf(rB.z, w1v[6], a); a = fmaf(rB.w, w1v[7], a);
            wt[jj] = a;
        }
        *(float4*)&swt[warp][0][k*8 + 4*h] = make_float4(wt[0], wt[1], wt[2], wt[3]);
    }
    {
        float w1v[8];
        #pragma unroll
        for (int j = 0; j < 8; j++) w1v[j] = fmaxf(w1B[j] + tw[j], 0.f);
        float wt[4];
        #pragma unroll
        for (int jj = 0; jj < 4; jj++) {
            int j = 4*h + jj;
            float4 rA = *(const float4*)&sWw2[j*8];
            float4 rB = *(const float4*)&sWw2[j*8 + 4];
            float a = bwr[jj];
            a = fmaf(rA.x, w1v[0], a); a = fmaf(rA.y, w1v[1], a);
            a = fmaf(rA.z, w1v[2], a); a = fmaf(rA.w, w1v[3], a);
            a = fmaf(rB.x, w1v[4], a); a = fmaf(rB.y, w1v[5], a);
            a = fmaf(rB.z, w1v[6], a); a = fmaf(rB.w, w1v[7], a);
            wt[jj] = a;
        }
        *(float4*)&swt[warp][1][k*8 + 4*h] = make_float4(wt[0], wt[1], wt[2], wt[3]);
    }
    __syncwarp();

    // softmax over K, both points
    #pragma unroll
    for (int pt = 0; pt < 2; pt++) {
        float* swp = swt[warp][pt];
        int j = l >> 2, kq = l & 3;
        float v0 = swp[(4*kq+0)*8 + j];
        float v1 = swp[(4*kq+1)*8 + j];
        float v2 = swp[(4*kq+2)*8 + j];
        float v3 = swp[(4*kq+3)*8 + j];
        float mx = fmaxf(fmaxf(v0, v1), fmaxf(v2, v3));
        mx = fmaxf(mx, __shfl_xor_sync(0xffffffffu, mx, 1));
        mx = fmaxf(mx, __shfl_xor_sync(0xffffffffu, mx, 2));
        float e0 = __expf(v0 - mx), e1 = __expf(v1 - mx);
        float e2 = __expf(v2 - mx), e3 = __expf(v3 - mx);
        float sm = e0 + e1 + e2 + e3;
        sm += __shfl_xor_sync(0xffffffffu, sm, 1);
        sm += __shfl_xor_sync(0xffffffffu, sm, 2);
        float inv = __fdividef(1.f, sm);
        swp[(4*kq+0)*8 + j] = e0 * inv;
        swp[(4*kq+1)*8 + j] = e1 * inv;
        swp[(4*kq+2)*8 + j] = e2 * inv;
        swp[(4*kq+3)*8 + j] = e3 * inv;
    }
    __syncwarp();

    // phase 3: lane owns channels 2l, 2l+1; interleaved A/B L2 loads (MLP=2)
    int cc0 = 2*l;
    int j0 = cc0 & 7;
    float a0 = 0.f, a1 = 0.f, b0 = 0.f, b1 = 0.f;
    #pragma unroll
    for (int kk2 = 0; kk2 < 16; kk2++) {
        float2 wvA = *(const float2*)&swt[warp][0][kk2*8 + j0];
        float2 wvB = *(const float2*)&swt[warp][1][kk2*8 + j0];
        int rA = __shfl_sync(0xffffffffu, myidx, kk2);
        int rB = __shfl_sync(0xffffffffu, myidx, 16 + kk2);
        float2 vA = __ldg((const float2*)(g_kv + (rowb + rA)*128 + 64 + cc0));
        float2 vB = __ldg((const float2*)(g_kv + (rowb + rB)*128 + 64 + cc0));
        a0 = fmaf(wvA.x, vA.x, a0); a1 = fmaf(wvA.y, vA.y, a1);
        b0 = fmaf(wvB.x, vB.x, b0); b1 = fmaf(wvB.y, vB.y, b1);
    }

    float4 sm4 = *(const float4*)(g_smt + 4*l);
    float xa0 = lrelu(fmaf(sm4.x, a0, sm4.y));
    float xa1 = lrelu(fmaf(sm4.z, a1, sm4.w));
    float xb0 = lrelu(fmaf(sm4.x, b0, sm4.y));
    float xb1 = lrelu(fmaf(sm4.z, b1, sm4.w));
    *(float2*)&g_xm[pbaseA + cc0] = make_float2(xa0, xa1);
    *(float2*)&g_xm[pbaseB + cc0] = make_float2(xb0, xb1);
}

// ---------------- conv2 + residual + lrelu, tiled GEMM (256 threads) --------
__global__ void __launch_bounds__(256) k_out(float* __restrict__ out)
{
    __shared__ float sbuf[64*68];
    int t  = threadIdx.x;
    int b  = blockIdx.y;
    int n0 = blockIdx.x * 64;
    size_t base = (size_t)b*NPT + n0;

    int p = t & 63, chunk = t >> 6;
    #pragma unroll
    for (int j = 0; j < 4; j++) {
        int ch = chunk*16 + 4*j;
        float4 v = *(const float4*)&g_xm[(base + p)*64 + ch];
        sbuf[(ch+0)*68+p] = v.x;
        sbuf[(ch+1)*68+p] = v.y;
        sbuf[(ch+2)*68+p] = v.z;
        sbuf[(ch+3)*68+p] = v.w;
    }
    __syncthreads();

    int cc = t & 15, pg = t >> 4;
    int cb = 4*cc, pb = 4*pg;

    float a[4][4];
    #pragma unroll
    for (int x = 0; x < 4; x++)
        #pragma unroll
        for (int y = 0; y < 4; y++) a[x][y] = 0.f;

    #pragma unroll 8
    for (int c = 0; c < 64; c++) {
        float4 w  = *(const float4*)&g_W2T[c*64 + cb];
        float4 xv = *(const float4*)&sbuf[c*68 + pb];
        float wc[4] = {w.x,w.y,w.z,w.w};
        float xp[4] = {xv.x,xv.y,xv.z,xv.w};
        #pragma unroll
        for (int ch = 0; ch < 4; ch++)
            #pragma unroll
            for (int pp = 0; pp < 4; pp++)
                a[ch][pp] = fmaf(wc[ch], xp[pp], a[ch][pp]);
    }
    __syncthreads();

    float4 t2v = *(const float4*)&g_t2[cb];
    float tb[4] = {t2v.x, t2v.y, t2v.z, t2v.w};
    #pragma unroll
    for (int pp = 0; pp < 4; pp++) {
        float4 fv = *(const float4*)&g_f[(base + pb + pp)*64 + cb];
        float fr[4] = {fv.x, fv.y, fv.z, fv.w};
        #pragma unroll
        for (int ch = 0; ch < 4; ch++)
            sbuf[(cb+ch)*68 + pb + pp] = lrelu(a[ch][pp] + tb[ch] + fr[ch]);
    }
    __syncthreads();

    int cO = t >> 2, q = t & 3;
    #pragma unroll
    for (int i = 0; i < 4; i++) {
        float4 vq = *(const float4*)&sbuf[cO*68 + q*16 + 4*i];
        *(float4*)&out[((size_t)(b*64 + cO))*NPT + n0 + q*16 + 4*i] = vq;
    }
}

extern "C" void kernel_launch(void* const* d_in, const int* in_sizes, int n_in,
                              void* d_out, int out_size)
{
    const float* feature = (const float*)d_in[0];
    const float* xyz     = (const float*)d_in[1];
    const float* W1      = (const float*)d_in[2];
    const float* bn1     = (const float*)d_in[3];
    const float* Wq      = (const float*)d_in[4];
    const float* bq      = (const float*)d_in[5];
    const float* Wk      = (const float*)d_in[6];
    const float* bk      = (const float*)d_in[7];
    const float* Wv      = (const float*)d_in[8];
    const float* bv      = (const float*)d_in[9];
    const float* Wp1     = (const float*)d_in[10];
    const float* bnp1    = (const float*)d_in[11];
    const float* Wp2     = (const float*)d_in[12];
    const float* bp2     = (const float*)d_in[13];
    const float* bnw0    = (const float*)d_in[14];
    const float* Ww1     = (const float*)d_in[15];
    const float* bnw1    = (const float*)d_in[16];
    const float* Ww2     = (const float*)d_in[17];
    const float* bw2     = (const float*)d_in[18];
    const float* bn_mid  = (const float*)d_in[19];
    const float* W2      = (const float*)d_in[20];
    const float* bn2     = (const float*)d_in[21];
    const int*   nidx    = (const int*)d_in[22];
    float* out = (float*)d_out;

    k_prep<<<64, 64>>>(W1, bn1, Wq, bq, Wk, bk, Wv, bv, Wp1, bnp1, Wp2, bp2,
                       bnw0, Ww1, bnw1, Ww2, bw2, bn_mid, W2, bn2);
    dim3 gf(NPT/64, BB);
    k_proj<<<gf, 256>>>(feature, xyz);
    k_attn<<<(BB*NPT)/(WPB*2), 128>>>(nidx);
    k_out<<<gf, 256>>>(out);
}